// round 6
// baseline (speedup 1.0000x reference)
#include <cuda_runtime.h>
#include <cstdint>

#define B_  256
#define P_  196
#define E_  2048
#define A_  512
#define M_  (B_*P_)   // 50176 = 392*128
#define BK  32

// ---------------- device scratch (no allocs allowed) ----------------
__device__ float g_dec_att[B_*A_];            // dec@W_dec + b_dec + b_enc
__device__ __align__(16) float g_Wt[A_*E_];   // W_enc^T, tf32-RNA, k-interleaved
__device__ float g_partial[M_*4];             // per-128-col score partials

// ---------------- helpers ----------------
__device__ __forceinline__ uint32_t smem_u32(const void* p) {
    uint32_t a;
    asm("{ .reg .u64 t; cvta.to.shared.u64 t, %1; cvt.u32.u64 %0, t; }"
        : "=r"(a) : "l"(p));
    return a;
}
__device__ __forceinline__ float to_tf32(float x) {
    float r; asm("cvt.rna.tf32.f32 %0, %1;" : "=f"(r) : "f"(x)); return r;
}
#define CP_ASYNC16(dst_u32, src_ptr) \
    asm volatile("cp.async.cg.shared.global [%0], [%1], 16;" \
                 :: "r"(dst_u32), "l"(src_ptr) : "memory")
#define CP_COMMIT()  asm volatile("cp.async.commit_group;" ::: "memory")
#define CP_WAIT0()   asm volatile("cp.async.wait_group 0;" ::: "memory")

__device__ __forceinline__ void mma_tf32(float* d, float a0, float a1, float a2,
                                         float a3, float b0, float b1) {
    asm volatile(
        "mma.sync.aligned.m16n8k8.row.col.f32.tf32.tf32.f32 "
        "{%0,%1,%2,%3}, {%4,%5,%6,%7}, {%8,%9}, {%0,%1,%2,%3};"
        : "+f"(d[0]), "+f"(d[1]), "+f"(d[2]), "+f"(d[3])
        : "r"(__float_as_uint(a0)), "r"(__float_as_uint(a1)),
          "r"(__float_as_uint(a2)), "r"(__float_as_uint(a3)),
          "r"(__float_as_uint(b0)), "r"(__float_as_uint(b1)));
}

// ---------------------------------------------------------------------------
// prep: blocks [0,1024) transpose W_enc -> g_Wt (tf32-RNA, k-interleaved);
//       blocks [1024,1056) compute dec_att.
// k-interleave within each 32-group: k' = (k%4)*8 + k/4.
// ---------------------------------------------------------------------------
__global__ __launch_bounds__(1024)
void prep_kernel(const float* __restrict__ W_enc,
                 const float* __restrict__ dec_h,
                 const float* __restrict__ W_dec,
                 const float* __restrict__ b_dec,
                 const float* __restrict__ b_enc) {
    __shared__ float t[32][33];
    __shared__ float s_h[8][512];
    int bid = blockIdx.x;
    int tid = threadIdx.x;
    if (bid < 1024) {
        int tx = tid & 31, ty = tid >> 5;
        int kt = (bid & 63) * 32, nt = (bid >> 6) * 32;
        t[ty][tx] = W_enc[(size_t)(kt + ty) * A_ + nt + tx];
        __syncthreads();
        // element (n = nt+ty, k = kt+tx) -> permuted k' within the 32-group
        int kp = kt + (tx & 3) * 8 + (tx >> 2);
        g_Wt[(size_t)(nt + ty) * E_ + kp] = to_tf32(t[tx][ty]);
    } else {
        int b0 = (bid - 1024) * 8;
        for (int i = tid; i < 8 * 512; i += 1024)
            s_h[i >> 9][i & 511] = dec_h[(b0 + (i >> 9)) * 512 + (i & 511)];
        __syncthreads();
        if (tid < 512) {
            int a = tid;
            float acc[8];
#pragma unroll
            for (int bb = 0; bb < 8; bb++) acc[bb] = 0.f;
            for (int d = 0; d < 512; d++) {
                float w = W_dec[d * A_ + a];
#pragma unroll
                for (int bb = 0; bb < 8; bb++)
                    acc[bb] = fmaf(s_h[bb][d], w, acc[bb]);
            }
            float bias = b_dec[a] + b_enc[a];
#pragma unroll
            for (int bb = 0; bb < 8; bb++)
                g_dec_att[(b0 + bb) * A_ + a] = acc[bb] + bias;
        }
    }
}

// ---------------------------------------------------------------------------
// Fused scores GEMM on the tensor pipe (mma.sync tf32).
// CTA: 128m x 128n x 32k, 8 warps (2m x 4n), warp tile 64x32 = 4x4 m16n8k8.
// K-interleaved smem: thread's 8 k-values contiguous -> v4 fragment loads
// (24 v4 LDS/warp/ktile instead of 96 scalar). All LDS/STS conflict-free.
// Epilogue: relu(C + dec_att)·W_att -> g_partial[row][nTile].
// ---------------------------------------------------------------------------
#define SPAD    36
#define TILE_F  (128*SPAD)                 // 4608 floats per matrix tile
#define STAGE_F (2*TILE_F)                 // 9216 (A+B)
#define OFF_DEC (2*STAGE_F)                // float index 18432
#define OFF_WATT (OFF_DEC + 256)
#define OFF_RED  (OFF_WATT + 128)
#define SMEM_FLOATS (OFF_RED + 512)
#define SMEM_BYTES  (SMEM_FLOATS * 4)      // 77,312 B

__global__ __launch_bounds__(256)
void scores_mma(const float* __restrict__ enc, const float* __restrict__ W_att) {
    extern __shared__ float sm[];
    const uint32_t sb = smem_u32(sm);

    const int tid  = threadIdx.x;
    const int lane = tid & 31, wid = tid >> 5;
    const int qr = lane >> 2, qc = lane & 3;
    const int wm = wid >> 2, wn = wid & 3;          // 2 x 4 warp grid
    const int nT = blockIdx.x, mT = blockIdx.y;
    const int mBase = mT * 128, nBase = nT * 128;
    const int b0 = mBase / P_;

    const int rowb = tid >> 3, c4 = tid & 7;        // load mapping

    float* s_dec  = sm + OFF_DEC;
    float* s_watt = sm + OFF_WATT;
    float* s_red  = sm + OFF_RED;

    // ---------------- prologue: stage 0 ----------------
    {   // A: LDG + cvt.rna + permuted scalar STS (value j -> col j*8 + c4)
#pragma unroll
        for (int i = 0; i < 4; i++) {
            int r = rowb + 32 * i;
            float4 v = *(const float4*)(enc + (size_t)(mBase + r) * E_ + c4 * 4);
            float* dst = sm + r * SPAD + c4;
            dst[0]  = to_tf32(v.x);
            dst[8]  = to_tf32(v.y);
            dst[16] = to_tf32(v.z);
            dst[24] = to_tf32(v.w);
        }
        // B: cp.async from pre-permuted g_Wt; rows nBase+n
#pragma unroll
        for (int i = 0; i < 4; i++) {
            int n = rowb + 32 * i;
            CP_ASYNC16(sb + (uint32_t)(TILE_F * 4 + n * (SPAD * 4) + c4 * 16),
                       g_Wt + (size_t)(nBase + n) * E_ + c4 * 4);
        }
        CP_COMMIT();
    }
    // dec rows (2 batches) + W_att slice for this CTA's 128 cols
    {
        int bb = b0 + (tid >> 7);
        if (bb >= B_) bb = B_ - 1;
        s_dec[tid] = g_dec_att[bb * A_ + nBase + (tid & 127)];
        if (tid < 128) s_watt[tid] = W_att[nBase + tid];
    }
    CP_WAIT0();
    __syncthreads();

    float acc[4][4][4];
#pragma unroll
    for (int mi = 0; mi < 4; mi++)
#pragma unroll
        for (int ni = 0; ni < 4; ni++)
#pragma unroll
            for (int j = 0; j < 4; j++) acc[mi][ni][j] = 0.f;

    // ---------------- main loop ----------------
    for (int kt = 0; kt < E_ / BK; kt++) {
        const float* Ac = sm + (kt & 1) * STAGE_F;
        const float* Bc = Ac + TILE_F;
        float4 areg[4];
        const int k0n = (kt + 1) * BK;
        const bool more = (kt < E_ / BK - 1);

        if (more) {
#pragma unroll
            for (int i = 0; i < 4; i++)
                areg[i] = *(const float4*)(enc + (size_t)(mBase + rowb + 32 * i) * E_
                                           + k0n + c4 * 4);
            uint32_t bdst = sb + ((kt & 1) ^ 1) * (STAGE_F * 4) + TILE_F * 4;
#pragma unroll
            for (int i = 0; i < 4; i++) {
                int n = rowb + 32 * i;
                CP_ASYNC16(bdst + (uint32_t)(n * (SPAD * 4) + c4 * 16),
                           g_Wt + (size_t)(nBase + n) * E_ + k0n + c4 * 4);
            }
            CP_COMMIT();
        }

        // two halves: h=0 covers ks 0,1 (t 0..3); h=1 covers ks 2,3 (t 4..7)
#pragma unroll
        for (int h = 0; h < 2; h++) {
            float4 ar0[4], ar8[4], bb[4];
            const int fcol = qc * 8 + 4 * h;
#pragma unroll
            for (int mi = 0; mi < 4; mi++) {
                const float* ap = Ac + (wm * 64 + mi * 16 + qr) * SPAD + fcol;
                ar0[mi] = *(const float4*)ap;
                ar8[mi] = *(const float4*)(ap + 8 * SPAD);
            }
#pragma unroll
            for (int ni = 0; ni < 4; ni++)
                bb[ni] = *(const float4*)(Bc + (wn * 32 + ni * 8 + qr) * SPAD + fcol);
#pragma unroll
            for (int mi = 0; mi < 4; mi++)
#pragma unroll
                for (int ni = 0; ni < 4; ni++) {
                    mma_tf32(acc[mi][ni], ar0[mi].x, ar8[mi].x, ar0[mi].y,
                             ar8[mi].y, bb[ni].x, bb[ni].y);
                    mma_tf32(acc[mi][ni], ar0[mi].z, ar8[mi].z, ar0[mi].w,
                             ar8[mi].w, bb[ni].z, bb[ni].w);
                }
        }

        if (more) {
            float* An = sm + ((kt & 1) ^ 1) * STAGE_F;
#pragma unroll
            for (int i = 0; i < 4; i++) {
                float* dst = An + (rowb + 32 * i) * SPAD + c4;
                dst[0]  = to_tf32(areg[i].x);
                dst[8]  = to_tf32(areg[i].y);
                dst[16] = to_tf32(areg[i].z);
                dst[24] = to_tf32(areg[i].w);
            }
            CP_WAIT0();
        }
        __syncthreads();
    }

    // ---------------- epilogue: relu(+dec)·W_att, per-row partials ----------------
#pragma unroll
    for (int mi = 0; mi < 4; mi++) {
#pragma unroll
        for (int half = 0; half < 2; half++) {
            int rl = wm * 64 + mi * 16 + qr + half * 8;
            int bloc = (mBase + rl) / P_ - b0;          // 0 or 1
            const float* drow = s_dec + bloc * 128;
            float s = 0.f;
#pragma unroll
            for (int ni = 0; ni < 4; ni++) {
#pragma unroll
                for (int j = 0; j < 2; j++) {
                    int c = wn * 32 + ni * 8 + qc * 2 + j;
                    float v = acc[mi][ni][half * 2 + j] + drow[c];
                    v = fmaxf(v, 0.f);
                    s = fmaf(v, s_watt[c], s);
                }
            }
            s += __shfl_xor_sync(0xffffffffu, s, 1);
            s += __shfl_xor_sync(0xffffffffu, s, 2);
            if (qc == 0) s_red[rl * 4 + wn] = s;
        }
    }
    __syncthreads();
    if (tid < 128) {
        const float* p = s_red + tid * 4;
        g_partial[(size_t)(mBase + tid) * 4 + nT] = p[0] + p[1] + p[2] + p[3];
    }
}

// ---------------------------------------------------------------------------
// softmax over P=196 per batch (sums the 4 col-chunk partials; b_att cancels)
// ---------------------------------------------------------------------------
__global__ void softmax_kernel(float* __restrict__ alpha_out) {
    __shared__ float s_red[256];
    int b = blockIdx.x, tid = threadIdx.x;
    float sc = 0.f;
    float v  = -1e30f;
    if (tid < P_) {
        const float* p = &g_partial[(size_t)(b * P_ + tid) * 4];
        sc = p[0] + p[1] + p[2] + p[3];
        v  = sc;
    }
    s_red[tid] = v;
    __syncthreads();
    for (int o = 128; o > 0; o >>= 1) {
        if (tid < o) s_red[tid] = fmaxf(s_red[tid], s_red[tid + o]);
        __syncthreads();
    }
    float mx = s_red[0];
    __syncthreads();
    float e = (tid < P_) ? __expf(sc - mx) : 0.f;
    s_red[tid] = e;
    __syncthreads();
    for (int o = 128; o > 0; o >>= 1) {
        if (tid < o) s_red[tid] += s_red[tid + o];
        __syncthreads();
    }
    float inv = 1.f / s_red[0];
    if (tid < P_) alpha_out[b * P_ + tid] = e * inv;
}

// ---------------------------------------------------------------------------
// context[b,:] = alpha[b,:] @ enc[b]   (float4, 4-way ILP; 196 = 49*4)
// ---------------------------------------------------------------------------
__global__ void context_kernel(const float* __restrict__ enc,
                               const float* __restrict__ alpha,
                               float* __restrict__ ctx) {
    __shared__ float s_a[P_];
    int b = blockIdx.y;
    for (int i = threadIdx.x; i < P_; i += 128) s_a[i] = alpha[b * P_ + i];
    __syncthreads();
    int e4 = blockIdx.x * 128 + threadIdx.x;   // 0..511
    const float4* base = (const float4*)(enc + (size_t)b * P_ * E_) + e4;
    float4 a0 = {0, 0, 0, 0}, a1 = {0, 0, 0, 0};
    float4 a2 = {0, 0, 0, 0}, a3 = {0, 0, 0, 0};
    for (int p = 0; p < P_; p += 4) {
        float4 v0 = base[(size_t)p * (E_ / 4)];
        float4 v1 = base[(size_t)(p + 1) * (E_ / 4)];
        float4 v2 = base[(size_t)(p + 2) * (E_ / 4)];
        float4 v3 = base[(size_t)(p + 3) * (E_ / 4)];
        float w0 = s_a[p], w1 = s_a[p + 1], w2 = s_a[p + 2], w3 = s_a[p + 3];
        a0.x = fmaf(w0, v0.x, a0.x); a0.y = fmaf(w0, v0.y, a0.y);
        a0.z = fmaf(w0, v0.z, a0.z); a0.w = fmaf(w0, v0.w, a0.w);
        a1.x = fmaf(w1, v1.x, a1.x); a1.y = fmaf(w1, v1.y, a1.y);
        a1.z = fmaf(w1, v1.z, a1.z); a1.w = fmaf(w1, v1.w, a1.w);
        a2.x = fmaf(w2, v2.x, a2.x); a2.y = fmaf(w2, v2.y, a2.y);
        a2.z = fmaf(w2, v2.z, a2.z); a2.w = fmaf(w2, v2.w, a2.w);
        a3.x = fmaf(w3, v3.x, a3.x); a3.y = fmaf(w3, v3.y, a3.y);
        a3.z = fmaf(w3, v3.z, a3.z); a3.w = fmaf(w3, v3.w, a3.w);
    }
    float4 r = { (a0.x + a1.x) + (a2.x + a3.x),
                 (a0.y + a1.y) + (a2.y + a3.y),
                 (a0.z + a1.z) + (a2.z + a3.z),
                 (a0.w + a1.w) + (a2.w + a3.w) };
    ((float4*)(ctx + (size_t)b * E_))[e4] = r;
}

// ---------------------------------------------------------------------------
extern "C" void kernel_launch(void* const* d_in, const int* in_sizes, int n_in,
                              void* d_out, int out_size) {
    const float* enc   = (const float*)d_in[0];
    const float* dech  = (const float*)d_in[1];
    const float* W_enc = (const float*)d_in[2];
    const float* b_enc = (const float*)d_in[3];
    const float* W_dec = (const float*)d_in[4];
    const float* b_dec = (const float*)d_in[5];
    const float* W_att = (const float*)d_in[6];
    // d_in[7] = b_att: constant shift, cancels in softmax.

    float* ctx   = (float*)d_out;            // [256, 2048]
    float* alpha = (float*)d_out + B_ * E_;  // [256, 196]

    cudaFuncSetAttribute(scores_mma, cudaFuncAttributeMaxDynamicSharedMemorySize,
                         SMEM_BYTES);

    prep_kernel<<<1056, 1024>>>(W_enc, dech, W_dec, b_dec, b_enc);
    scores_mma<<<dim3(4, 392), 256, SMEM_BYTES>>>(enc, W_att);
    softmax_kernel<<<B_, 256>>>(alpha);
    context_kernel<<<dim3(4, B_), 128>>>(enc, alpha, ctx);
}

// round 7
// speedup vs baseline: 1.1142x; 1.1142x over previous
#include <cuda_runtime.h>
#include <cstdint>

#define B_  256
#define P_  196
#define E_  2048
#define A_  512
#define M_  (B_*P_)   // 50176 = 392*128
#define BK  64

// ---------------- device scratch (no allocs allowed) ----------------
__device__ float g_dec_att[B_*A_];            // dec@W_dec + b_dec + b_enc
__device__ __align__(16) float g_Wt[A_*E_];   // W_enc^T, tf32-RNA, [n][k]
__device__ float g_partial[M_*4];             // per-128-col score partials

// ---------------- helpers ----------------
__device__ __forceinline__ uint32_t smem_u32(const void* p) {
    uint32_t a;
    asm("{ .reg .u64 t; cvta.to.shared.u64 t, %1; cvt.u32.u64 %0, t; }"
        : "=r"(a) : "l"(p));
    return a;
}
__device__ __forceinline__ float to_tf32(float x) {
    float r; asm("cvt.rna.tf32.f32 %0, %1;" : "=f"(r) : "f"(x)); return r;
}
#define CP_ASYNC16(dst_u32, src_ptr) \
    asm volatile("cp.async.cg.shared.global [%0], [%1], 16;" \
                 :: "r"(dst_u32), "l"(src_ptr) : "memory")
#define CP_COMMIT()  asm volatile("cp.async.commit_group;" ::: "memory")
#define CP_WAIT0()   asm volatile("cp.async.wait_group 0;" ::: "memory")

__device__ __forceinline__ void mma_tf32(float* d, const float* a, const float* b) {
    asm volatile(
        "mma.sync.aligned.m16n8k8.row.col.f32.tf32.tf32.f32 "
        "{%0,%1,%2,%3}, {%4,%5,%6,%7}, {%8,%9}, {%0,%1,%2,%3};"
        : "+f"(d[0]), "+f"(d[1]), "+f"(d[2]), "+f"(d[3])
        : "r"(__float_as_uint(a[0])), "r"(__float_as_uint(a[1])),
          "r"(__float_as_uint(a[2])), "r"(__float_as_uint(a[3])),
          "r"(__float_as_uint(b[0])), "r"(__float_as_uint(b[1])));
}

// ---------------------------------------------------------------------------
// prep: blocks [0,1024) transpose W_enc -> g_Wt (tf32-RNA, plain layout);
//       blocks [1024,1056) compute dec_att.
// ---------------------------------------------------------------------------
__global__ __launch_bounds__(1024)
void prep_kernel(const float* __restrict__ W_enc,
                 const float* __restrict__ dec_h,
                 const float* __restrict__ W_dec,
                 const float* __restrict__ b_dec,
                 const float* __restrict__ b_enc) {
    __shared__ float t[32][33];
    __shared__ float s_h[8][512];
    int bid = blockIdx.x;
    int tid = threadIdx.x;
    if (bid < 1024) {
        int tx = tid & 31, ty = tid >> 5;
        int kt = (bid & 63) * 32, nt = (bid >> 6) * 32;
        t[ty][tx] = W_enc[(size_t)(kt + ty) * A_ + nt + tx];
        __syncthreads();
        g_Wt[(size_t)(nt + ty) * E_ + kt + tx] = to_tf32(t[tx][ty]);
    } else {
        int b0 = (bid - 1024) * 8;
        for (int i = tid; i < 8 * 512; i += 1024)
            s_h[i >> 9][i & 511] = dec_h[(b0 + (i >> 9)) * 512 + (i & 511)];
        __syncthreads();
        if (tid < 512) {
            int a = tid;
            float acc[8];
#pragma unroll
            for (int bb = 0; bb < 8; bb++) acc[bb] = 0.f;
            for (int d = 0; d < 512; d++) {
                float w = W_dec[d * A_ + a];
#pragma unroll
                for (int bb = 0; bb < 8; bb++)
                    acc[bb] = fmaf(s_h[bb][d], w, acc[bb]);
            }
            float bias = b_dec[a] + b_enc[a];
#pragma unroll
            for (int bb = 0; bb < 8; bb++)
                g_dec_att[(b0 + bb) * A_ + a] = acc[bb] + bias;
        }
    }
}

// ---------------------------------------------------------------------------
// Fused scores GEMM on the tensor pipe (mma.sync tf32).
// CTA: 128m x 128n x 64k, 8 warps (2m x 4n), warp tile 64x32 = 4x4 m16n8k8.
// BK=64 halves the per-ktile barrier/wait overhead vs BK=32.
// SPAD=68; all LDS/STS conflict-free per 8-lane phase. 142.8 KB smem, 1 CTA/SM.
// Epilogue: relu(C + dec_att)·W_att -> g_partial[row][nTile].
// ---------------------------------------------------------------------------
#define SPAD    68
#define TILE_F  (128*SPAD)                 // 8704 floats per matrix tile
#define STAGE_F (2*TILE_F)                 // 17408 (A+B)
#define OFF_DEC (2*STAGE_F)                // float index 34816
#define OFF_WATT (OFF_DEC + 256)
#define OFF_RED  (OFF_WATT + 128)
#define SMEM_FLOATS (OFF_RED + 512)
#define SMEM_BYTES  (SMEM_FLOATS * 4)      // 142,848 B

__global__ __launch_bounds__(256)
void scores_mma(const float* __restrict__ enc, const float* __restrict__ W_att) {
    extern __shared__ float sm[];
    const uint32_t sb = smem_u32(sm);

    const int tid  = threadIdx.x;
    const int lane = tid & 31, wid = tid >> 5;
    const int qr = lane >> 2, qc = lane & 3;
    const int wm = wid >> 2, wn = wid & 3;          // 2 x 4 warp grid
    const int nT = blockIdx.x, mT = blockIdx.y;
    const int mBase = mT * 128, nBase = nT * 128;
    const int b0 = mBase / P_;

    // load mapping: 128 rows x 16 float4-cols, 8 chunks of 256 threads
    const int rowb = tid >> 4, c4 = tid & 15;

    float* s_dec  = sm + OFF_DEC;
    float* s_watt = sm + OFF_WATT;
    float* s_red  = sm + OFF_RED;

    // ---------------- prologue: stage 0 ----------------
    {   // A: LDG + cvt.rna + STS.128 (layout [m][68])
#pragma unroll
        for (int i = 0; i < 8; i++) {
            int r = rowb + 16 * i;
            float4 v = *(const float4*)(enc + (size_t)(mBase + r) * E_ + c4 * 4);
            float4 t = { to_tf32(v.x), to_tf32(v.y), to_tf32(v.z), to_tf32(v.w) };
            *(float4*)(sm + r * SPAD + c4 * 4) = t;
        }
        // B: cp.async from g_Wt (layout [n][68]); rows nBase+n
#pragma unroll
        for (int i = 0; i < 8; i++) {
            int n = rowb + 16 * i;
            CP_ASYNC16(sb + (uint32_t)(TILE_F * 4 + n * (SPAD * 4) + c4 * 16),
                       g_Wt + (size_t)(nBase + n) * E_ + c4 * 4);
        }
        CP_COMMIT();
    }
    // dec rows (2 batches) + W_att slice for this CTA's 128 cols
    {
        int bb = b0 + (tid >> 7);
        if (bb >= B_) bb = B_ - 1;
        s_dec[tid] = g_dec_att[bb * A_ + nBase + (tid & 127)];
        if (tid < 128) s_watt[tid] = W_att[nBase + tid];
    }
    CP_WAIT0();
    __syncthreads();

    float acc[4][4][4];
#pragma unroll
    for (int mi = 0; mi < 4; mi++)
#pragma unroll
        for (int ni = 0; ni < 4; ni++)
#pragma unroll
            for (int j = 0; j < 4; j++) acc[mi][ni][j] = 0.f;

    // ---------------- main loop (32 iterations of BK=64) ----------------
    for (int kt = 0; kt < E_ / BK; kt++) {
        const float* Ac = sm + (kt & 1) * STAGE_F;
        const float* Bc = Ac + TILE_F;
        float4 areg[8];
        const int k0n = (kt + 1) * BK;
        const bool more = (kt < E_ / BK - 1);

        if (more) {
#pragma unroll
            for (int i = 0; i < 8; i++)
                areg[i] = *(const float4*)(enc + (size_t)(mBase + rowb + 16 * i) * E_
                                           + k0n + c4 * 4);
            uint32_t bdst = sb + ((kt & 1) ^ 1) * (STAGE_F * 4) + TILE_F * 4;
#pragma unroll
            for (int i = 0; i < 8; i++) {
                int n = rowb + 16 * i;
                CP_ASYNC16(bdst + (uint32_t)(n * (SPAD * 4) + c4 * 16),
                           g_Wt + (size_t)(nBase + n) * E_ + k0n + c4 * 4);
            }
            CP_COMMIT();
        }

#pragma unroll
        for (int ks = 0; ks < 8; ks++) {
            float a[4][4], b[4][2];
#pragma unroll
            for (int mi = 0; mi < 4; mi++) {
                const float* ap = Ac + (wm * 64 + mi * 16 + qr) * SPAD + ks * 8 + qc;
                a[mi][0] = ap[0];
                a[mi][1] = ap[8 * SPAD];
                a[mi][2] = ap[4];
                a[mi][3] = ap[8 * SPAD + 4];
            }
#pragma unroll
            for (int ni = 0; ni < 4; ni++) {
                const float* bp = Bc + (wn * 32 + ni * 8 + qr) * SPAD + ks * 8 + qc;
                b[ni][0] = bp[0];
                b[ni][1] = bp[4];
            }
#pragma unroll
            for (int mi = 0; mi < 4; mi++)
#pragma unroll
                for (int ni = 0; ni < 4; ni++)
                    mma_tf32(acc[mi][ni], a[mi], b[ni]);
        }

        if (more) {
            float* An = sm + ((kt & 1) ^ 1) * STAGE_F;
#pragma unroll
            for (int i = 0; i < 8; i++) {
                float4 t = { to_tf32(areg[i].x), to_tf32(areg[i].y),
                             to_tf32(areg[i].z), to_tf32(areg[i].w) };
                *(float4*)(An + (rowb + 16 * i) * SPAD + c4 * 4) = t;
            }
            CP_WAIT0();
        }
        __syncthreads();
    }

    // ---------------- epilogue: relu(+dec)·W_att, per-row partials ----------------
#pragma unroll
    for (int mi = 0; mi < 4; mi++) {
#pragma unroll
        for (int half = 0; half < 2; half++) {
            int rl = wm * 64 + mi * 16 + qr + half * 8;
            int bloc = (mBase + rl) / P_ - b0;          // 0 or 1
            const float* drow = s_dec + bloc * 128;
            float s = 0.f;
#pragma unroll
            for (int ni = 0; ni < 4; ni++) {
#pragma unroll
                for (int j = 0; j < 2; j++) {
                    int c = wn * 32 + ni * 8 + qc * 2 + j;
                    float v = acc[mi][ni][half * 2 + j] + drow[c];
                    v = fmaxf(v, 0.f);
                    s = fmaf(v, s_watt[c], s);
                }
            }
            s += __shfl_xor_sync(0xffffffffu, s, 1);
            s += __shfl_xor_sync(0xffffffffu, s, 2);
            if (qc == 0) s_red[rl * 4 + wn] = s;
        }
    }
    __syncthreads();
    if (tid < 128) {
        const float* p = s_red + tid * 4;
        g_partial[(size_t)(mBase + tid) * 4 + nT] = p[0] + p[1] + p[2] + p[3];
    }
}

// ---------------------------------------------------------------------------
// softmax over P=196 per batch (sums the 4 col-chunk partials; b_att cancels)
// ---------------------------------------------------------------------------
__global__ void softmax_kernel(float* __restrict__ alpha_out) {
    __shared__ float s_red[256];
    int b = blockIdx.x, tid = threadIdx.x;
    float sc = 0.f;
    float v  = -1e30f;
    if (tid < P_) {
        const float* p = &g_partial[(size_t)(b * P_ + tid) * 4];
        sc = p[0] + p[1] + p[2] + p[3];
        v  = sc;
    }
    s_red[tid] = v;
    __syncthreads();
    for (int o = 128; o > 0; o >>= 1) {
        if (tid < o) s_red[tid] = fmaxf(s_red[tid], s_red[tid + o]);
        __syncthreads();
    }
    float mx = s_red[0];
    __syncthreads();
    float e = (tid < P_) ? __expf(sc - mx) : 0.f;
    s_red[tid] = e;
    __syncthreads();
    for (int o = 128; o > 0; o >>= 1) {
        if (tid < o) s_red[tid] += s_red[tid + o];
        __syncthreads();
    }
    float inv = 1.f / s_red[0];
    if (tid < P_) alpha_out[b * P_ + tid] = e * inv;
}

// ---------------------------------------------------------------------------
// context[b,:] = alpha[b,:] @ enc[b]   (float4, 4-way ILP; 196 = 49*4)
// ---------------------------------------------------------------------------
__global__ void context_kernel(const float* __restrict__ enc,
                               const float* __restrict__ alpha,
                               float* __restrict__ ctx) {
    __shared__ float s_a[P_];
    int b = blockIdx.y;
    for (int i = threadIdx.x; i < P_; i += 128) s_a[i] = alpha[b * P_ + i];
    __syncthreads();
    int e4 = blockIdx.x * 128 + threadIdx.x;   // 0..511
    const float4* base = (const float4*)(enc + (size_t)b * P_ * E_) + e4;
    float4 a0 = {0, 0, 0, 0}, a1 = {0, 0, 0, 0};
    float4 a2 = {0, 0, 0, 0}, a3 = {0, 0, 0, 0};
    for (int p = 0; p < P_; p += 4) {
        float4 v0 = base[(size_t)p * (E_ / 4)];
        float4 v1 = base[(size_t)(p + 1) * (E_ / 4)];
        float4 v2 = base[(size_t)(p + 2) * (E_ / 4)];
        float4 v3 = base[(size_t)(p + 3) * (E_ / 4)];
        float w0 = s_a[p], w1 = s_a[p + 1], w2 = s_a[p + 2], w3 = s_a[p + 3];
        a0.x = fmaf(w0, v0.x, a0.x); a0.y = fmaf(w0, v0.y, a0.y);
        a0.z = fmaf(w0, v0.z, a0.z); a0.w = fmaf(w0, v0.w, a0.w);
        a1.x = fmaf(w1, v1.x, a1.x); a1.y = fmaf(w1, v1.y, a1.y);
        a1.z = fmaf(w1, v1.z, a1.z); a1.w = fmaf(w1, v1.w, a1.w);
        a2.x = fmaf(w2, v2.x, a2.x); a2.y = fmaf(w2, v2.y, a2.y);
        a2.z = fmaf(w2, v2.z, a2.z); a2.w = fmaf(w2, v2.w, a2.w);
        a3.x = fmaf(w3, v3.x, a3.x); a3.y = fmaf(w3, v3.y, a3.y);
        a3.z = fmaf(w3, v3.z, a3.z); a3.w = fmaf(w3, v3.w, a3.w);
    }
    float4 r = { (a0.x + a1.x) + (a2.x + a3.x),
                 (a0.y + a1.y) + (a2.y + a3.y),
                 (a0.z + a1.z) + (a2.z + a3.z),
                 (a0.w + a1.w) + (a2.w + a3.w) };
    ((float4*)(ctx + (size_t)b * E_))[e4] = r;
}

// ---------------------------------------------------------------------------
extern "C" void kernel_launch(void* const* d_in, const int* in_sizes, int n_in,
                              void* d_out, int out_size) {
    const float* enc   = (const float*)d_in[0];
    const float* dech  = (const float*)d_in[1];
    const float* W_enc = (const float*)d_in[2];
    const float* b_enc = (const float*)d_in[3];
    const float* W_dec = (const float*)d_in[4];
    const float* b_dec = (const float*)d_in[5];
    const float* W_att = (const float*)d_in[6];
    // d_in[7] = b_att: constant shift, cancels in softmax.

    float* ctx   = (float*)d_out;            // [256, 2048]
    float* alpha = (float*)d_out + B_ * E_;  // [256, 196]

    cudaFuncSetAttribute(scores_mma, cudaFuncAttributeMaxDynamicSharedMemorySize,
                         SMEM_BYTES);

    prep_kernel<<<1056, 1024>>>(W_enc, dech, W_dec, b_dec, b_enc);
    scores_mma<<<dim3(4, 392), 256, SMEM_BYTES>>>(enc, W_att);
    softmax_kernel<<<B_, 256>>>(alpha);
    context_kernel<<<dim3(4, B_), 128>>>(enc, alpha, ctx);
}

// round 8
// speedup vs baseline: 1.3493x; 1.2110x over previous
#include <cuda_runtime.h>
#include <cuda_fp16.h>
#include <cstdint>

#define B_  256
#define P_  196
#define E_  2048
#define A_  512
#define M_  (B_*P_)   // 50176 = 392*128
#define BK  64        // k-halfs per tile

// ---------------- device scratch (no allocs allowed) ----------------
__device__ float g_dec_att[B_*A_];              // dec@W_dec + b_dec + b_enc
__device__ __align__(16) __half g_Wt[A_*E_];    // W_enc^T as fp16, [n][k]
__device__ float g_partial[M_*4];               // per-128-col score partials

// ---------------- helpers ----------------
__device__ __forceinline__ uint32_t smem_u32(const void* p) {
    uint32_t a;
    asm("{ .reg .u64 t; cvta.to.shared.u64 t, %1; cvt.u32.u64 %0, t; }"
        : "=r"(a) : "l"(p));
    return a;
}
__device__ __forceinline__ uint32_t pack_h2(float x, float y) {
    __half2 p = __floats2half2_rn(x, y);
    return *reinterpret_cast<uint32_t*>(&p);
}
#define CP_ASYNC16(dst_u32, src_ptr) \
    asm volatile("cp.async.cg.shared.global [%0], [%1], 16;" \
                 :: "r"(dst_u32), "l"(src_ptr) : "memory")
#define CP_COMMIT()  asm volatile("cp.async.commit_group;" ::: "memory")
#define CP_WAIT0()   asm volatile("cp.async.wait_group 0;" ::: "memory")

#define LDSM_X4(r0, r1, r2, r3, addr) \
    asm volatile("ldmatrix.sync.aligned.m8n8.x4.shared.b16 {%0,%1,%2,%3}, [%4];" \
                 : "=r"(r0), "=r"(r1), "=r"(r2), "=r"(r3) : "r"(addr))

#define MMA_F16(d, a0, a1, a2, a3, b0, b1) \
    asm volatile("mma.sync.aligned.m16n8k16.row.col.f32.f16.f16.f32 " \
                 "{%0,%1,%2,%3}, {%4,%5,%6,%7}, {%8,%9}, {%0,%1,%2,%3};" \
                 : "+f"((d)[0]), "+f"((d)[1]), "+f"((d)[2]), "+f"((d)[3]) \
                 : "r"(a0), "r"(a1), "r"(a2), "r"(a3), "r"(b0), "r"(b1))

// ---------------------------------------------------------------------------
// prep: blocks [0,1024) transpose W_enc -> g_Wt (fp16 RNE, [n][k]);
//       blocks [1024,1056) compute dec_att (fp32).
// ---------------------------------------------------------------------------
__global__ __launch_bounds__(1024)
void prep_kernel(const float* __restrict__ W_enc,
                 const float* __restrict__ dec_h,
                 const float* __restrict__ W_dec,
                 const float* __restrict__ b_dec,
                 const float* __restrict__ b_enc) {
    __shared__ float t[32][33];
    __shared__ float s_h[8][512];
    int bid = blockIdx.x;
    int tid = threadIdx.x;
    if (bid < 1024) {
        int tx = tid & 31, ty = tid >> 5;
        int kt = (bid & 63) * 32, nt = (bid >> 6) * 32;
        t[ty][tx] = W_enc[(size_t)(kt + ty) * A_ + nt + tx];
        __syncthreads();
        g_Wt[(size_t)(nt + ty) * E_ + kt + tx] = __float2half_rn(t[tx][ty]);
    } else {
        int b0 = (bid - 1024) * 8;
        for (int i = tid; i < 8 * 512; i += 1024)
            s_h[i >> 9][i & 511] = dec_h[(b0 + (i >> 9)) * 512 + (i & 511)];
        __syncthreads();
        if (tid < 512) {
            int a = tid;
            float acc[8];
#pragma unroll
            for (int bb = 0; bb < 8; bb++) acc[bb] = 0.f;
            for (int d = 0; d < 512; d++) {
                float w = W_dec[d * A_ + a];
#pragma unroll
                for (int bb = 0; bb < 8; bb++)
                    acc[bb] = fmaf(s_h[bb][d], w, acc[bb]);
            }
            float bias = b_dec[a] + b_enc[a];
#pragma unroll
            for (int bb = 0; bb < 8; bb++)
                g_dec_att[(b0 + bb) * A_ + a] = acc[bb] + bias;
        }
    }
}

// ---------------------------------------------------------------------------
// Fused scores GEMM, fp16 tensor path (mma.sync m16n8k16, fp32 accum).
// CTA: 128m x 128n x 64k, 8 warps (2m x 4n), warp tile 64x32.
// Smem tiles: [row][72 halfs] (144 B pitch) — conflict-free STS.128 + LDSM.
// A: LDG fp32 + cvt + STS; B: cp.async from pre-converted g_Wt.
// Fragments via ldmatrix.x4. Epilogue: relu(C+dec)·W_att -> g_partial.
// ---------------------------------------------------------------------------
#define PITCH   144                        // bytes per smem row (72 halfs)
#define TILE_B  (128*PITCH)                // 18432 B per matrix tile
#define STAGE_B (2*TILE_B)                 // 36864 B (A+B)
#define OFF_F32 (2*STAGE_B)                // 73728: float scratch region
#define SMEM_BYTES (OFF_F32 + 896*4)       // 77,312 B

__global__ __launch_bounds__(256)
void scores_mma(const float* __restrict__ enc, const float* __restrict__ W_att) {
    extern __shared__ char sm[];
    const uint32_t sb = smem_u32(sm);

    const int tid  = threadIdx.x;
    const int lane = tid & 31, wid = tid >> 5;
    const int qr = lane >> 2, qc = lane & 3;
    const int wm = wid >> 2, wn = wid & 3;          // 2 x 4 warp grid
    const int nT = blockIdx.x, mT = blockIdx.y;
    const int mBase = mT * 128, nBase = nT * 128;
    const int b0 = mBase / P_;

    // producer mapping: each thread fills half a row (32 halfs = 64 B)
    const int rowp = tid >> 1, hsel = tid & 1;

    float* s_dec  = (float*)(sm + OFF_F32);         // 256
    float* s_watt = s_dec + 256;                    // 128
    float* s_red  = s_watt + 128;                   // 512

    // ldmatrix thread-invariant byte offsets (within a tile)
    const uint32_t a_off = (uint32_t)((wm * 64 + (lane & 15)) * PITCH
                                      + (lane >> 4) * 16);
    const uint32_t b_off = (uint32_t)((wn * 32 + (lane & 7) + ((lane >> 4) << 3))
                                      * PITCH + ((lane >> 3) & 1) * 16);

    // ---------------- prologue: stage 0 ----------------
    {
        const float* asrc = enc + (size_t)(mBase + rowp) * E_ + hsel * 32;
        uint32_t h[16];
#pragma unroll
        for (int i = 0; i < 8; i++) {
            float4 v = *(const float4*)(asrc + i * 4);
            h[2 * i]     = pack_h2(v.x, v.y);
            h[2 * i + 1] = pack_h2(v.z, v.w);
        }
        char* adst = sm + rowp * PITCH + hsel * 64;
#pragma unroll
        for (int j = 0; j < 4; j++)
            *(uint4*)(adst + j * 16) = *(uint4*)(h + 4 * j);

        const __half* bsrc = g_Wt + (size_t)(nBase + rowp) * E_ + hsel * 32;
        uint32_t bdst = sb + TILE_B + (uint32_t)(rowp * PITCH + hsel * 64);
#pragma unroll
        for (int j = 0; j < 4; j++)
            CP_ASYNC16(bdst + j * 16, bsrc + j * 8);
        CP_COMMIT();
    }
    // dec rows (2 batches) + W_att slice
    {
        int bb = b0 + (tid >> 7);
        if (bb >= B_) bb = B_ - 1;
        s_dec[tid] = g_dec_att[bb * A_ + nBase + (tid & 127)];
        if (tid < 128) s_watt[tid] = W_att[nBase + tid];
    }
    CP_WAIT0();
    __syncthreads();

    float acc[4][4][4];
#pragma unroll
    for (int mi = 0; mi < 4; mi++)
#pragma unroll
        for (int ni = 0; ni < 4; ni++)
#pragma unroll
            for (int j = 0; j < 4; j++) acc[mi][ni][j] = 0.f;

    // ---------------- main loop (32 iterations of BK=64) ----------------
    for (int kt = 0; kt < E_ / BK; kt++) {
        const uint32_t aBase = sb + (kt & 1) * STAGE_B;
        const uint32_t bBase = aBase + TILE_B;
        const int k0n = (kt + 1) * BK;
        const bool more = (kt < E_ / BK - 1);
        float4 areg[8];

        if (more) {
            const float* asrc = enc + (size_t)(mBase + rowp) * E_ + k0n + hsel * 32;
#pragma unroll
            for (int i = 0; i < 8; i++)
                areg[i] = *(const float4*)(asrc + i * 4);
            const __half* bsrc = g_Wt + (size_t)(nBase + rowp) * E_ + k0n + hsel * 32;
            uint32_t bdst = sb + ((kt & 1) ^ 1) * STAGE_B + TILE_B
                          + (uint32_t)(rowp * PITCH + hsel * 64);
#pragma unroll
            for (int j = 0; j < 4; j++)
                CP_ASYNC16(bdst + j * 16, bsrc + j * 8);
            CP_COMMIT();
        }

#pragma unroll
        for (int ks = 0; ks < 4; ks++) {
            uint32_t af[4][4], bf[2][4];
#pragma unroll
            for (int mi = 0; mi < 4; mi++)
                LDSM_X4(af[mi][0], af[mi][1], af[mi][2], af[mi][3],
                        aBase + a_off + (uint32_t)(mi * 16 * PITCH + ks * 32));
#pragma unroll
            for (int np = 0; np < 2; np++)
                LDSM_X4(bf[np][0], bf[np][1], bf[np][2], bf[np][3],
                        bBase + b_off + (uint32_t)(np * 16 * PITCH + ks * 32));
#pragma unroll
            for (int mi = 0; mi < 4; mi++)
#pragma unroll
                for (int ni = 0; ni < 4; ni++)
                    MMA_F16(acc[mi][ni],
                            af[mi][0], af[mi][1], af[mi][2], af[mi][3],
                            bf[ni >> 1][(ni & 1) * 2], bf[ni >> 1][(ni & 1) * 2 + 1]);
        }

        if (more) {
            char* adst = sm + ((kt & 1) ^ 1) * STAGE_B + rowp * PITCH + hsel * 64;
            uint32_t h[16];
#pragma unroll
            for (int i = 0; i < 8; i++) {
                h[2 * i]     = pack_h2(areg[i].x, areg[i].y);
                h[2 * i + 1] = pack_h2(areg[i].z, areg[i].w);
            }
#pragma unroll
            for (int j = 0; j < 4; j++)
                *(uint4*)(adst + j * 16) = *(uint4*)(h + 4 * j);
            CP_WAIT0();
        }
        __syncthreads();
    }

    // ---------------- epilogue: relu(+dec)·W_att, per-row partials ----------------
#pragma unroll
    for (int mi = 0; mi < 4; mi++) {
#pragma unroll
        for (int half = 0; half < 2; half++) {
            int rl = wm * 64 + mi * 16 + qr + half * 8;
            int bloc = (mBase + rl) / P_ - b0;          // 0 or 1
            const float* drow = s_dec + bloc * 128;
            float s = 0.f;
#pragma unroll
            for (int ni = 0; ni < 4; ni++) {
#pragma unroll
                for (int j = 0; j < 2; j++) {
                    int c = wn * 32 + ni * 8 + qc * 2 + j;
                    float v = acc[mi][ni][half * 2 + j] + drow[c];
                    v = fmaxf(v, 0.f);
                    s = fmaf(v, s_watt[c], s);
                }
            }
            s += __shfl_xor_sync(0xffffffffu, s, 1);
            s += __shfl_xor_sync(0xffffffffu, s, 2);
            if (qc == 0) s_red[rl * 4 + wn] = s;
        }
    }
    __syncthreads();
    if (tid < 128) {
        const float* p = s_red + tid * 4;
        g_partial[(size_t)(mBase + tid) * 4 + nT] = p[0] + p[1] + p[2] + p[3];
    }
}

// ---------------------------------------------------------------------------
// softmax over P=196 per batch (sums the 4 col-chunk partials; b_att cancels)
// ---------------------------------------------------------------------------
__global__ void softmax_kernel(float* __restrict__ alpha_out) {
    __shared__ float s_red[256];
    int b = blockIdx.x, tid = threadIdx.x;
    float sc = 0.f;
    float v  = -1e30f;
    if (tid < P_) {
        const float* p = &g_partial[(size_t)(b * P_ + tid) * 4];
        sc = p[0] + p[1] + p[2] + p[3];
        v  = sc;
    }
    s_red[tid] = v;
    __syncthreads();
    for (int o = 128; o > 0; o >>= 1) {
        if (tid < o) s_red[tid] = fmaxf(s_red[tid], s_red[tid + o]);
        __syncthreads();
    }
    float mx = s_red[0];
    __syncthreads();
    float e = (tid < P_) ? __expf(sc - mx) : 0.f;
    s_red[tid] = e;
    __syncthreads();
    for (int o = 128; o > 0; o >>= 1) {
        if (tid < o) s_red[tid] += s_red[tid + o];
        __syncthreads();
    }
    float inv = 1.f / s_red[0];
    if (tid < P_) alpha_out[b * P_ + tid] = e * inv;
}

// ---------------------------------------------------------------------------
// context[b,:] = alpha[b,:] @ enc[b]   (float4, 4-way ILP; 196 = 49*4)
// ---------------------------------------------------------------------------
__global__ void context_kernel(const float* __restrict__ enc,
                               const float* __restrict__ alpha,
                               float* __restrict__ ctx) {
    __shared__ float s_a[P_];
    int b = blockIdx.y;
    for (int i = threadIdx.x; i < P_; i += 128) s_a[i] = alpha[b * P_ + i];
    __syncthreads();
    int e4 = blockIdx.x * 128 + threadIdx.x;   // 0..511
    const float4* base = (const float4*)(enc + (size_t)b * P_ * E_) + e4;
    float4 a0 = {0, 0, 0, 0}, a1 = {0, 0, 0, 0};
    float4 a2 = {0, 0, 0, 0}, a3 = {0, 0, 0, 0};
    for (int p = 0; p < P_; p += 4) {
        float4 v0 = base[(size_t)p * (E_ / 4)];
        float4 v1 = base[(size_t)(p + 1) * (E_ / 4)];
        float4 v2 = base[(size_t)(p + 2) * (E_ / 4)];
        float4 v3 = base[(size_t)(p + 3) * (E_ / 4)];
        float w0 = s_a[p], w1 = s_a[p + 1], w2 = s_a[p + 2], w3 = s_a[p + 3];
        a0.x = fmaf(w0, v0.x, a0.x); a0.y = fmaf(w0, v0.y, a0.y);
        a0.z = fmaf(w0, v0.z, a0.z); a0.w = fmaf(w0, v0.w, a0.w);
        a1.x = fmaf(w1, v1.x, a1.x); a1.y = fmaf(w1, v1.y, a1.y);
        a1.z = fmaf(w1, v1.z, a1.z); a1.w = fmaf(w1, v1.w, a1.w);
        a2.x = fmaf(w2, v2.x, a2.x); a2.y = fmaf(w2, v2.y, a2.y);
        a2.z = fmaf(w2, v2.z, a2.z); a2.w = fmaf(w2, v2.w, a2.w);
        a3.x = fmaf(w3, v3.x, a3.x); a3.y = fmaf(w3, v3.y, a3.y);
        a3.z = fmaf(w3, v3.z, a3.z); a3.w = fmaf(w3, v3.w, a3.w);
    }
    float4 r = { (a0.x + a1.x) + (a2.x + a3.x),
                 (a0.y + a1.y) + (a2.y + a3.y),
                 (a0.z + a1.z) + (a2.z + a3.z),
                 (a0.w + a1.w) + (a2.w + a3.w) };
    ((float4*)(ctx + (size_t)b * E_))[e4] = r;
}

// ---------------------------------------------------------------------------
extern "C" void kernel_launch(void* const* d_in, const int* in_sizes, int n_in,
                              void* d_out, int out_size) {
    const float* enc   = (const float*)d_in[0];
    const float* dech  = (const float*)d_in[1];
    const float* W_enc = (const float*)d_in[2];
    const float* b_enc = (const float*)d_in[3];
    const float* W_dec = (const float*)d_in[4];
    const float* b_dec = (const float*)d_in[5];
    const float* W_att = (const float*)d_in[6];
    // d_in[7] = b_att: constant shift, cancels in softmax.

    float* ctx   = (float*)d_out;            // [256, 2048]
    float* alpha = (float*)d_out + B_ * E_;  // [256, 196]

    cudaFuncSetAttribute(scores_mma, cudaFuncAttributeMaxDynamicSharedMemorySize,
                         SMEM_BYTES);

    prep_kernel<<<1056, 1024>>>(W_enc, dech, W_dec, b_dec, b_enc);
    scores_mma<<<dim3(4, 392), 256, SMEM_BYTES>>>(enc, W_att);
    softmax_kernel<<<B_, 256>>>(alpha);
    context_kernel<<<dim3(4, B_), 128>>>(enc, alpha, ctx);
}

// round 9
// speedup vs baseline: 1.6875x; 1.2506x over previous
#include <cuda_runtime.h>
#include <cuda_fp16.h>
#include <cstdint>

#define B_  256
#define P_  196
#define E_  2048
#define A_  512
#define M_  (B_*P_)   // 50176 = 392*128
#define BK  32        // k-halfs per tile

// ---------------- device scratch (no allocs allowed) ----------------
__device__ float g_dec_att[B_*A_];              // dec@W_dec + b_dec + b_enc
__device__ __align__(16) __half g_Wt[A_*E_];    // W_enc^T as fp16, [n][k]
__device__ float g_partial[M_*4];               // per-128-col score partials

// ---------------- helpers ----------------
__device__ __forceinline__ uint32_t smem_u32(const void* p) {
    uint32_t a;
    asm("{ .reg .u64 t; cvta.to.shared.u64 t, %1; cvt.u32.u64 %0, t; }"
        : "=r"(a) : "l"(p));
    return a;
}
__device__ __forceinline__ uint32_t pack_h2(float x, float y) {
    __half2 p = __floats2half2_rn(x, y);
    return *reinterpret_cast<uint32_t*>(&p);
}
#define CP_ASYNC16(dst_u32, src_ptr) \
    asm volatile("cp.async.cg.shared.global [%0], [%1], 16;" \
                 :: "r"(dst_u32), "l"(src_ptr) : "memory")
#define CP_COMMIT()  asm volatile("cp.async.commit_group;" ::: "memory")
#define CP_WAIT0()   asm volatile("cp.async.wait_group 0;" ::: "memory")

#define LDSM_X4(r0, r1, r2, r3, addr) \
    asm volatile("ldmatrix.sync.aligned.m8n8.x4.shared.b16 {%0,%1,%2,%3}, [%4];" \
                 : "=r"(r0), "=r"(r1), "=r"(r2), "=r"(r3) : "r"(addr))

#define MMA_F16(d, a0, a1, a2, a3, b0, b1) \
    asm volatile("mma.sync.aligned.m16n8k16.row.col.f32.f16.f16.f32 " \
                 "{%0,%1,%2,%3}, {%4,%5,%6,%7}, {%8,%9}, {%0,%1,%2,%3};" \
                 : "+f"((d)[0]), "+f"((d)[1]), "+f"((d)[2]), "+f"((d)[3]) \
                 : "r"(a0), "r"(a1), "r"(a2), "r"(a3), "r"(b0), "r"(b1))

// ---------------------------------------------------------------------------
// prep: blocks [0,1024) transpose W_enc -> g_Wt (fp16 RNE, [n][k]);
//       blocks [1024,1056) compute dec_att (fp32).
// ---------------------------------------------------------------------------
__global__ __launch_bounds__(1024)
void prep_kernel(const float* __restrict__ W_enc,
                 const float* __restrict__ dec_h,
                 const float* __restrict__ W_dec,
                 const float* __restrict__ b_dec,
                 const float* __restrict__ b_enc) {
    __shared__ float t[32][33];
    __shared__ float s_h[8][512];
    int bid = blockIdx.x;
    int tid = threadIdx.x;
    if (bid < 1024) {
        int tx = tid & 31, ty = tid >> 5;
        int kt = (bid & 63) * 32, nt = (bid >> 6) * 32;
        t[ty][tx] = W_enc[(size_t)(kt + ty) * A_ + nt + tx];
        __syncthreads();
        g_Wt[(size_t)(nt + ty) * E_ + kt + tx] = __float2half_rn(t[tx][ty]);
    } else {
        int b0 = (bid - 1024) * 8;
        for (int i = tid; i < 8 * 512; i += 1024)
            s_h[i >> 9][i & 511] = dec_h[(b0 + (i >> 9)) * 512 + (i & 511)];
        __syncthreads();
        if (tid < 512) {
            int a = tid;
            float acc[8];
#pragma unroll
            for (int bb = 0; bb < 8; bb++) acc[bb] = 0.f;
            for (int d = 0; d < 512; d++) {
                float w = W_dec[d * A_ + a];
#pragma unroll
                for (int bb = 0; bb < 8; bb++)
                    acc[bb] = fmaf(s_h[bb][d], w, acc[bb]);
            }
            float bias = b_dec[a] + b_enc[a];
#pragma unroll
            for (int bb = 0; bb < 8; bb++)
                g_dec_att[(b0 + bb) * A_ + a] = acc[bb] + bias;
        }
    }
}

// ---------------------------------------------------------------------------
// Fused scores GEMM, fp16 tensor path (mma.sync m16n8k16, fp32 accum).
// CTA: 128m x 128n x 32k, 8 warps (2m x 4n), warp tile 64x32.
// Smem rows: 80 B pitch (64 B data + 16 pad) — conflict-free for LDSM
// (banks 0,20,8,28,16,4,24,12), A STS.64 producer, B cp.async.
// 44.5 KB smem + <=128 regs -> 2 CTAs/SM for cross-CTA latency hiding.
// Epilogue: relu(C+dec)·W_att -> g_partial.
// ---------------------------------------------------------------------------
#define PITCH   80                         // bytes per smem row (40 halfs)
#define TILE_B  (128*PITCH)                // 10240 B per matrix tile
#define STAGE_B (2*TILE_B)                 // 20480 B (A+B)
#define OFF_F32 (2*STAGE_B)                // 40960: float scratch region
#define SMEM_BYTES (OFF_F32 + 896*4)       // 44,544 B

__global__ __launch_bounds__(256, 2)
void scores_mma(const float* __restrict__ enc, const float* __restrict__ W_att) {
    extern __shared__ char sm[];
    const uint32_t sb = smem_u32(sm);

    const int tid  = threadIdx.x;
    const int lane = tid & 31, wid = tid >> 5;
    const int qr = lane >> 2, qc = lane & 3;
    const int wm = wid >> 2, wn = wid & 3;          // 2 x 4 warp grid
    const int nT = blockIdx.x, mT = blockIdx.y;
    const int mBase = mT * 128, nBase = nT * 128;
    const int b0 = mBase / P_;

    // A producer mapping: 4 passes, pass i: row = (tid>>3)+32i, 4 fp32 cols
    const int arow = tid >> 3, ac = tid & 7;

    float* s_dec  = (float*)(sm + OFF_F32);         // 256
    float* s_watt = s_dec + 256;                    // 128
    float* s_red  = s_watt + 128;                   // 512

    // ldmatrix thread-invariant byte offsets (within a tile)
    const uint32_t a_off = (uint32_t)((wm * 64 + (lane & 15)) * PITCH
                                      + (lane >> 4) * 16);
    const uint32_t b_off = (uint32_t)((wn * 32 + (lane & 7) + ((lane >> 4) << 3))
                                      * PITCH + ((lane >> 3) & 1) * 16);

    // ---------------- prologue: stage 0 ----------------
    {
#pragma unroll
        for (int i = 0; i < 4; i++) {
            int r = arow + 32 * i;
            float4 v = *(const float4*)(enc + (size_t)(mBase + r) * E_ + ac * 4);
            uint2 h = { pack_h2(v.x, v.y), pack_h2(v.z, v.w) };
            *(uint2*)(sm + r * PITCH + ac * 8) = h;
        }
        if (tid < 128) {
            const __half* bsrc = g_Wt + (size_t)(nBase + tid) * E_;
            uint32_t bdst = sb + TILE_B + (uint32_t)(tid * PITCH);
#pragma unroll
            for (int j = 0; j < 4; j++)
                CP_ASYNC16(bdst + j * 16, bsrc + j * 8);
        }
        CP_COMMIT();
    }
    // dec rows (2 batches) + W_att slice
    {
        int bb = b0 + (tid >> 7);
        if (bb >= B_) bb = B_ - 1;
        s_dec[tid] = g_dec_att[bb * A_ + nBase + (tid & 127)];
        if (tid < 128) s_watt[tid] = W_att[nBase + tid];
    }
    CP_WAIT0();
    __syncthreads();

    float acc[4][4][4];
#pragma unroll
    for (int mi = 0; mi < 4; mi++)
#pragma unroll
        for (int ni = 0; ni < 4; ni++)
#pragma unroll
            for (int j = 0; j < 4; j++) acc[mi][ni][j] = 0.f;

    // ---------------- main loop (64 iterations of BK=32) ----------------
    for (int kt = 0; kt < E_ / BK; kt++) {
        const uint32_t aBase = sb + (kt & 1) * STAGE_B;
        const uint32_t bBase = aBase + TILE_B;
        const int k0n = (kt + 1) * BK;
        const bool more = (kt < E_ / BK - 1);
        uint2 ah[4];

        if (more) {
            // A prefetch: LDG + immediate cvt to half (8 u32 staged)
#pragma unroll
            for (int i = 0; i < 4; i++) {
                float4 v = *(const float4*)(enc + (size_t)(mBase + arow + 32 * i) * E_
                                            + k0n + ac * 4);
                ah[i].x = pack_h2(v.x, v.y);
                ah[i].y = pack_h2(v.z, v.w);
            }
            if (tid < 128) {
                const __half* bsrc = g_Wt + (size_t)(nBase + tid) * E_ + k0n;
                uint32_t bdst = sb + ((kt & 1) ^ 1) * STAGE_B + TILE_B
                              + (uint32_t)(tid * PITCH);
#pragma unroll
                for (int j = 0; j < 4; j++)
                    CP_ASYNC16(bdst + j * 16, bsrc + j * 8);
            }
            CP_COMMIT();
        }

#pragma unroll
        for (int ks = 0; ks < 2; ks++) {
            uint32_t af[4][4], bf[2][4];
#pragma unroll
            for (int mi = 0; mi < 4; mi++)
                LDSM_X4(af[mi][0], af[mi][1], af[mi][2], af[mi][3],
                        aBase + a_off + (uint32_t)(mi * 16 * PITCH + ks * 32));
#pragma unroll
            for (int np = 0; np < 2; np++)
                LDSM_X4(bf[np][0], bf[np][1], bf[np][2], bf[np][3],
                        bBase + b_off + (uint32_t)(np * 16 * PITCH + ks * 32));
#pragma unroll
            for (int mi = 0; mi < 4; mi++)
#pragma unroll
                for (int ni = 0; ni < 4; ni++)
                    MMA_F16(acc[mi][ni],
                            af[mi][0], af[mi][1], af[mi][2], af[mi][3],
                            bf[ni >> 1][(ni & 1) * 2], bf[ni >> 1][(ni & 1) * 2 + 1]);
        }

        if (more) {
            char* An = sm + ((kt & 1) ^ 1) * STAGE_B;
#pragma unroll
            for (int i = 0; i < 4; i++)
                *(uint2*)(An + (arow + 32 * i) * PITCH + ac * 8) = ah[i];
            CP_WAIT0();
        }
        __syncthreads();
    }

    // ---------------- epilogue: relu(+dec)·W_att, per-row partials ----------------
#pragma unroll
    for (int mi = 0; mi < 4; mi++) {
#pragma unroll
        for (int half = 0; half < 2; half++) {
            int rl = wm * 64 + mi * 16 + qr + half * 8;
            int bloc = (mBase + rl) / P_ - b0;          // 0 or 1
            const float* drow = s_dec + bloc * 128;
            float s = 0.f;
#pragma unroll
            for (int ni = 0; ni < 4; ni++) {
#pragma unroll
                for (int j = 0; j < 2; j++) {
                    int c = wn * 32 + ni * 8 + qc * 2 + j;
                    float v = acc[mi][ni][half * 2 + j] + drow[c];
                    v = fmaxf(v, 0.f);
                    s = fmaf(v, s_watt[c], s);
                }
            }
            s += __shfl_xor_sync(0xffffffffu, s, 1);
            s += __shfl_xor_sync(0xffffffffu, s, 2);
            if (qc == 0) s_red[rl * 4 + wn] = s;
        }
    }
    __syncthreads();
    if (tid < 128) {
        const float* p = s_red + tid * 4;
        g_partial[(size_t)(mBase + tid) * 4 + nT] = p[0] + p[1] + p[2] + p[3];
    }
}

// ---------------------------------------------------------------------------
// softmax over P=196 per batch (sums the 4 col-chunk partials; b_att cancels)
// ---------------------------------------------------------------------------
__global__ void softmax_kernel(float* __restrict__ alpha_out) {
    __shared__ float s_red[256];
    int b = blockIdx.x, tid = threadIdx.x;
    float sc = 0.f;
    float v  = -1e30f;
    if (tid < P_) {
        const float* p = &g_partial[(size_t)(b * P_ + tid) * 4];
        sc = p[0] + p[1] + p[2] + p[3];
        v  = sc;
    }
    s_red[tid] = v;
    __syncthreads();
    for (int o = 128; o > 0; o >>= 1) {
        if (tid < o) s_red[tid] = fmaxf(s_red[tid], s_red[tid + o]);
        __syncthreads();
    }
    float mx = s_red[0];
    __syncthreads();
    float e = (tid < P_) ? __expf(sc - mx) : 0.f;
    s_red[tid] = e;
    __syncthreads();
    for (int o = 128; o > 0; o >>= 1) {
        if (tid < o) s_red[tid] += s_red[tid + o];
        __syncthreads();
    }
    float inv = 1.f / s_red[0];
    if (tid < P_) alpha_out[b * P_ + tid] = e * inv;
}

// ---------------------------------------------------------------------------
// context[b,:] = alpha[b,:] @ enc[b]   (float4, 4-way ILP; 196 = 49*4)
// ---------------------------------------------------------------------------
__global__ void context_kernel(const float* __restrict__ enc,
                               const float* __restrict__ alpha,
                               float* __restrict__ ctx) {
    __shared__ float s_a[P_];
    int b = blockIdx.y;
    for (int i = threadIdx.x; i < P_; i += 128) s_a[i] = alpha[b * P_ + i];
    __syncthreads();
    int e4 = blockIdx.x * 128 + threadIdx.x;   // 0..511
    const float4* base = (const float4*)(enc + (size_t)b * P_ * E_) + e4;
    float4 a0 = {0, 0, 0, 0}, a1 = {0, 0, 0, 0};
    float4 a2 = {0, 0, 0, 0}, a3 = {0, 0, 0, 0};
    for (int p = 0; p < P_; p += 4) {
        float4 v0 = base[(size_t)p * (E_ / 4)];
        float4 v1 = base[(size_t)(p + 1) * (E_ / 4)];
        float4 v2 = base[(size_t)(p + 2) * (E_ / 4)];
        float4 v3 = base[(size_t)(p + 3) * (E_ / 4)];
        float w0 = s_a[p], w1 = s_a[p + 1], w2 = s_a[p + 2], w3 = s_a[p + 3];
        a0.x = fmaf(w0, v0.x, a0.x); a0.y = fmaf(w0, v0.y, a0.y);
        a0.z = fmaf(w0, v0.z, a0.z); a0.w = fmaf(w0, v0.w, a0.w);
        a1.x = fmaf(w1, v1.x, a1.x); a1.y = fmaf(w1, v1.y, a1.y);
        a1.z = fmaf(w1, v1.z, a1.z); a1.w = fmaf(w1, v1.w, a1.w);
        a2.x = fmaf(w2, v2.x, a2.x); a2.y = fmaf(w2, v2.y, a2.y);
        a2.z = fmaf(w2, v2.z, a2.z); a2.w = fmaf(w2, v2.w, a2.w);
        a3.x = fmaf(w3, v3.x, a3.x); a3.y = fmaf(w3, v3.y, a3.y);
        a3.z = fmaf(w3, v3.z, a3.z); a3.w = fmaf(w3, v3.w, a3.w);
    }
    float4 r = { (a0.x + a1.x) + (a2.x + a3.x),
                 (a0.y + a1.y) + (a2.y + a3.y),
                 (a0.z + a1.z) + (a2.z + a3.z),
                 (a0.w + a1.w) + (a2.w + a3.w) };
    ((float4*)(ctx + (size_t)b * E_))[e4] = r;
}

// ---------------------------------------------------------------------------
extern "C" void kernel_launch(void* const* d_in, const int* in_sizes, int n_in,
                              void* d_out, int out_size) {
    const float* enc   = (const float*)d_in[0];
    const float* dech  = (const float*)d_in[1];
    const float* W_enc = (const float*)d_in[2];
    const float* b_enc = (const float*)d_in[3];
    const float* W_dec = (const float*)d_in[4];
    const float* b_dec = (const float*)d_in[5];
    const float* W_att = (const float*)d_in[6];
    // d_in[7] = b_att: constant shift, cancels in softmax.

    float* ctx   = (float*)d_out;            // [256, 2048]
    float* alpha = (float*)d_out + B_ * E_;  // [256, 196]

    cudaFuncSetAttribute(scores_mma, cudaFuncAttributeMaxDynamicSharedMemorySize,
                         SMEM_BYTES);

    prep_kernel<<<1056, 1024>>>(W_enc, dech, W_dec, b_dec, b_enc);
    scores_mma<<<dim3(4, 392), 256, SMEM_BYTES>>>(enc, W_att);
    softmax_kernel<<<B_, 256>>>(alpha);
    context_kernel<<<dim3(4, B_), 128>>>(enc, alpha, ctx);
}